// round 7
// baseline (speedup 1.0000x reference)
#include <cuda_runtime.h>
#include <math.h>

#define DD 128
#define D4 32
#define MAX_NBR 1024
#define NTHR 256
#define NWARP 8

// ---- fused: scan + norms-on-the-fly + single-pass score/exp/accumulate ----
__global__ void __launch_bounds__(NTHR, 6) gat_kernel(
    const float* __restrict__ x, const float* __restrict__ adj,
    const float* __restrict__ beta, float* __restrict__ out, int N)
{
    __shared__ float4 xi4[D4];
    __shared__ float4 accs4[NWARP][D4];
    __shared__ int    nidx[MAX_NBR];
    __shared__ int    wsum[NWARP];
    __shared__ int    s_tot;
    __shared__ float  zred[NWARP];

    const int i    = blockIdx.x;
    const int tid  = threadIdx.x;
    const int lane = tid & 31;
    const int warp = tid >> 5;

    if (tid < D4) xi4[tid] = ((const float4*)x)[(size_t)i * D4 + tid];

    // ---- Phase 1: adj row scan in 2 batches of 4 tiles ----
    const int n4 = N >> 2;
    const float4* a4 = (const float4*)adj + (size_t)i * n4;

    unsigned mask = 0u;
#pragma unroll
    for (int half = 0; half < 2; ++half) {
        float4 a[4];
#pragma unroll
        for (int q = 0; q < 4; ++q) {
            int t = (half * 4 + q) * NTHR + tid;
            a[q] = (t < n4) ? a4[t] : make_float4(0.f, 0.f, 0.f, 0.f);
        }
#pragma unroll
        for (int q = 0; q < 4; ++q) {
            unsigned b = (a[q].x != 0.f ? 1u : 0u) | (a[q].y != 0.f ? 2u : 0u) |
                         (a[q].z != 0.f ? 4u : 0u) | (a[q].w != 0.f ? 8u : 0u);
            mask |= b << ((half * 4 + q) * 4);
        }
    }
    int c = __popc(mask);

    int p = c;
#pragma unroll
    for (int o = 1; o < 32; o <<= 1) {
        int v = __shfl_up_sync(0xffffffffu, p, o);
        if (lane >= o) p += v;
    }
    if (lane == 31) wsum[warp] = p;
    __syncthreads();
    if (tid == 0) {
        int run = 0;
#pragma unroll
        for (int w = 0; w < NWARP; ++w) { int v = wsum[w]; wsum[w] = run; run += v; }
        s_tot = run;
    }
    __syncthreads();

    {
        int off = wsum[warp] + (p - c);
        unsigned msk = mask;
        while (msk) {
            int b = __ffs(msk) - 1;
            msk &= msk - 1u;
            int col = 4 * (((b >> 2) * NTHR) + tid) + (b & 3);
            if (off < MAX_NBR) nidx[off] = col;
            ++off;
        }
    }
    __syncthreads();
    const int m = min(s_tot, (int)MAX_NBR);

    // ---- Phase 2: per-warp ni from shared x_i ----
    const float b  = beta[0];
    const float4 xi = xi4[lane];
    float ni;
    {
        float s = xi.x * xi.x + xi.y * xi.y + xi.z * xi.z + xi.w * xi.w;
#pragma unroll
        for (int o = 16; o > 0; o >>= 1) s += __shfl_xor_sync(0xffffffffu, s, o);
        ni = sqrtf(s);
    }

    // ---- Phase 3: single pass, 3 neighbors/warp/round, norms on the fly ----
    float4 acc = make_float4(0.f, 0.f, 0.f, 0.f);
    float  z   = 0.f;

    for (int k = warp * 3; k < m; k += 3 * NWARP) {
        const bool h1 = (k + 1 < m);
        const bool h2 = (k + 2 < m);
        int j0 = nidx[k];
        int j1 = h1 ? nidx[k + 1] : j0;
        int j2 = h2 ? nidx[k + 2] : j0;

        float4 x0 = ((const float4*)x)[(size_t)j0 * D4 + lane];
        float4 x1 = ((const float4*)x)[(size_t)j1 * D4 + lane];
        float4 x2 = ((const float4*)x)[(size_t)j2 * D4 + lane];

        float d0 = x0.x * xi.x + x0.y * xi.y + x0.z * xi.z + x0.w * xi.w;
        float d1 = x1.x * xi.x + x1.y * xi.y + x1.z * xi.z + x1.w * xi.w;
        float d2 = x2.x * xi.x + x2.y * xi.y + x2.z * xi.z + x2.w * xi.w;
        float s0 = x0.x * x0.x + x0.y * x0.y + x0.z * x0.z + x0.w * x0.w;
        float s1 = x1.x * x1.x + x1.y * x1.y + x1.z * x1.z + x1.w * x1.w;
        float s2 = x2.x * x2.x + x2.y * x2.y + x2.z * x2.z + x2.w * x2.w;
#pragma unroll
        for (int o = 16; o > 0; o >>= 1) {
            d0 += __shfl_xor_sync(0xffffffffu, d0, o);
            d1 += __shfl_xor_sync(0xffffffffu, d1, o);
            d2 += __shfl_xor_sync(0xffffffffu, d2, o);
            s0 += __shfl_xor_sync(0xffffffffu, s0, o);
            s1 += __shfl_xor_sync(0xffffffffu, s1, o);
            s2 += __shfl_xor_sync(0xffffffffu, s2, o);
        }

        float e0 =      __expf(b * __fdividef(d0, ni * sqrtf(s0) + 1e-7f));
        float e1 = h1 ? __expf(b * __fdividef(d1, ni * sqrtf(s1) + 1e-7f)) : 0.f;
        float e2 = h2 ? __expf(b * __fdividef(d2, ni * sqrtf(s2) + 1e-7f)) : 0.f;

        acc.x = fmaf(e0, x0.x, fmaf(e1, x1.x, fmaf(e2, x2.x, acc.x)));
        acc.y = fmaf(e0, x0.y, fmaf(e1, x1.y, fmaf(e2, x2.y, acc.y)));
        acc.z = fmaf(e0, x0.z, fmaf(e1, x1.z, fmaf(e2, x2.z, acc.z)));
        acc.w = fmaf(e0, x0.w, fmaf(e1, x1.w, fmaf(e2, x2.w, acc.w)));
        z += e0 + e1 + e2;
    }

    // ---- Phase 4: deterministic cross-warp combine ----
    accs4[warp][lane] = acc;
    if (lane == 0) zred[warp] = z;
    __syncthreads();

    if (tid < D4) {
        float4 s = make_float4(0.f, 0.f, 0.f, 0.f);
#pragma unroll
        for (int w = 0; w < NWARP; ++w) {
            float4 v = accs4[w][tid];
            s.x += v.x; s.y += v.y; s.z += v.z; s.w += v.w;
        }
        float Z = 0.f;
#pragma unroll
        for (int w = 0; w < NWARP; ++w) Z += zred[w];
        float invZ = 1.0f / Z;
        s.x *= invZ; s.y *= invZ; s.z *= invZ; s.w *= invZ;
        ((float4*)out)[(size_t)i * D4 + tid] = s;
    }
}

extern "C" void kernel_launch(void* const* d_in, const int* in_sizes, int n_in,
                              void* d_out, int out_size) {
    const float* x    = (const float*)d_in[0];
    const float* adj  = (const float*)d_in[1];
    const float* beta = (const float*)d_in[2];
    float* out = (float*)d_out;

    double asz = (double)in_sizes[1];
    int N = (int)(sqrt(asz) + 0.5);

    gat_kernel<<<N, NTHR>>>(x, adj, beta, out, N);
}

// round 8
// speedup vs baseline: 1.0764x; 1.0764x over previous
#include <cuda_runtime.h>
#include <math.h>

#define DD 128
#define D4 32
#define MAX_NBR 1024
#define NTHR 256
#define NWARP 8
#define GRID_P (148 * 6)

__device__ float g_norms[16384];

// ---- norms: 4 rows per warp, batched loads ----
__global__ void norms_kernel(const float* __restrict__ x, int N) {
    int wg   = blockIdx.x * (NTHR / 32) + (threadIdx.x >> 5);
    int lane = threadIdx.x & 31;
    int row0 = wg * 4;
    float4 v[4];
#pragma unroll
    for (int r = 0; r < 4; ++r) {
        int row = row0 + r;
        v[r] = (row < N) ? ((const float4*)x)[(size_t)row * D4 + lane]
                         : make_float4(0.f, 0.f, 0.f, 0.f);
    }
#pragma unroll
    for (int r = 0; r < 4; ++r) {
        float s = v[r].x * v[r].x + v[r].y * v[r].y + v[r].z * v[r].z + v[r].w * v[r].w;
#pragma unroll
        for (int o = 16; o > 0; o >>= 1) s += __shfl_xor_sync(0xffffffffu, s, o);
        if (lane == 0 && row0 + r < N) g_norms[row0 + r] = sqrtf(s);
    }
}

// ---- persistent fused kernel: loop rows with static partition ----
__global__ void __launch_bounds__(NTHR, 6) gat_kernel(
    const float* __restrict__ x, const float* __restrict__ adj,
    const float* __restrict__ beta, float* __restrict__ out, int N)
{
    __shared__ float4 xi4[D4];
    __shared__ float4 accs4[NWARP][D4];
    __shared__ int    nidx[MAX_NBR];
    __shared__ int    wsum[NWARP];
    __shared__ int    s_tot;
    __shared__ float  zred[NWARP];

    const int tid  = threadIdx.x;
    const int lane = tid & 31;
    const int warp = tid >> 5;
    const float b  = beta[0];
    const int n4   = N >> 2;

    for (int i = blockIdx.x; i < N; i += gridDim.x) {

        if (tid < D4) xi4[tid] = ((const float4*)x)[(size_t)i * D4 + tid];

        // ---- Phase 1: adj row scan (streaming loads, evict-first) ----
        const float4* a4 = (const float4*)adj + (size_t)i * n4;

        unsigned mask = 0u;
#pragma unroll
        for (int half = 0; half < 2; ++half) {
            float4 a[4];
#pragma unroll
            for (int q = 0; q < 4; ++q) {
                int t = (half * 4 + q) * NTHR + tid;
                a[q] = (t < n4) ? __ldcs(&a4[t]) : make_float4(0.f, 0.f, 0.f, 0.f);
            }
#pragma unroll
            for (int q = 0; q < 4; ++q) {
                unsigned bb = (a[q].x != 0.f ? 1u : 0u) | (a[q].y != 0.f ? 2u : 0u) |
                              (a[q].z != 0.f ? 4u : 0u) | (a[q].w != 0.f ? 8u : 0u);
                mask |= bb << ((half * 4 + q) * 4);
            }
        }
        int c = __popc(mask);

        int p = c;
#pragma unroll
        for (int o = 1; o < 32; o <<= 1) {
            int v = __shfl_up_sync(0xffffffffu, p, o);
            if (lane >= o) p += v;
        }
        if (lane == 31) wsum[warp] = p;
        __syncthreads();
        if (tid == 0) {
            int run = 0;
#pragma unroll
            for (int w = 0; w < NWARP; ++w) { int v = wsum[w]; wsum[w] = run; run += v; }
            s_tot = run;
        }
        __syncthreads();

        {
            int off = wsum[warp] + (p - c);
            unsigned msk = mask;
            while (msk) {
                int bit = __ffs(msk) - 1;
                msk &= msk - 1u;
                int col = 4 * (((bit >> 2) * NTHR) + tid) + (bit & 3);
                if (off < MAX_NBR) nidx[off] = col;
                ++off;
            }
        }
        __syncthreads();
        const int m = min(s_tot, (int)MAX_NBR);

        // ---- Phase 2: fused dot/exp/accumulate, 2 nbrs per warp per round ----
        const float ni  = g_norms[i];
        const float4 xi = xi4[lane];

        float4 acc = make_float4(0.f, 0.f, 0.f, 0.f);
        float  z   = 0.f;

        for (int k = warp * 2; k < m; k += 2 * NWARP) {
            const bool h1 = (k + 1 < m);
            int j0 = nidx[k];
            int j1 = h1 ? nidx[k + 1] : j0;

            float4 x0 = ((const float4*)x)[(size_t)j0 * D4 + lane];
            float4 x1 = ((const float4*)x)[(size_t)j1 * D4 + lane];
            float  n0 = g_norms[j0];
            float  n1 = g_norms[j1];

            float d0 = x0.x * xi.x + x0.y * xi.y + x0.z * xi.z + x0.w * xi.w;
            float d1 = x1.x * xi.x + x1.y * xi.y + x1.z * xi.z + x1.w * xi.w;
#pragma unroll
            for (int o = 16; o > 0; o >>= 1) {
                d0 += __shfl_xor_sync(0xffffffffu, d0, o);
                d1 += __shfl_xor_sync(0xffffffffu, d1, o);
            }

            float e0 =      __expf(b * __fdividef(d0, ni * n0 + 1e-7f));
            float e1 = h1 ? __expf(b * __fdividef(d1, ni * n1 + 1e-7f)) : 0.f;

            acc.x = fmaf(e0, x0.x, fmaf(e1, x1.x, acc.x));
            acc.y = fmaf(e0, x0.y, fmaf(e1, x1.y, acc.y));
            acc.z = fmaf(e0, x0.z, fmaf(e1, x1.z, acc.z));
            acc.w = fmaf(e0, x0.w, fmaf(e1, x1.w, acc.w));
            z += e0 + e1;
        }

        // ---- Phase 3: deterministic cross-warp combine ----
        accs4[warp][lane] = acc;
        if (lane == 0) zred[warp] = z;
        __syncthreads();

        if (tid < D4) {
            float4 s = make_float4(0.f, 0.f, 0.f, 0.f);
#pragma unroll
            for (int w = 0; w < NWARP; ++w) {
                float4 v = accs4[w][tid];
                s.x += v.x; s.y += v.y; s.z += v.z; s.w += v.w;
            }
            float Z = 0.f;
#pragma unroll
            for (int w = 0; w < NWARP; ++w) Z += zred[w];
            float invZ = 1.0f / Z;
            s.x *= invZ; s.y *= invZ; s.z *= invZ; s.w *= invZ;
            ((float4*)out)[(size_t)i * D4 + tid] = s;
        }
        __syncthreads();   // protect shared reuse next iteration
    }
}

extern "C" void kernel_launch(void* const* d_in, const int* in_sizes, int n_in,
                              void* d_out, int out_size) {
    const float* x    = (const float*)d_in[0];
    const float* adj  = (const float*)d_in[1];
    const float* beta = (const float*)d_in[2];
    float* out = (float*)d_out;

    double asz = (double)in_sizes[1];
    int N = (int)(sqrt(asz) + 0.5);

    int rows_per_block = (NTHR / 32) * 4;
    int nb = (N + rows_per_block - 1) / rows_per_block;
    norms_kernel<<<nb, NTHR>>>(x, N);

    int grid = (N < GRID_P) ? N : GRID_P;
    gat_kernel<<<grid, NTHR>>>(x, adj, beta, out, N);
}